// round 4
// baseline (speedup 1.0000x reference)
#include <cuda_runtime.h>
#include <cstdint>

// Problem constants (fixed by the dataset)
#define N_MAX 50000
#define E_MAX 800000
#define C_IN  128
#define C_HID 128
#define C_OUT 64

// ---------------- scratch (static __device__) ----------------
__device__ float g_h1[(size_t)N_MAX * C_HID];   // x @ W1
__device__ float g_a [(size_t)N_MAX * C_HID];   // relu(agg1 + b1)
__device__ float g_h2[(size_t)N_MAX * C_OUT];   // a @ W2
__device__ float g_dinv[N_MAX];
__device__ int   g_dege[N_MAX];                 // in-degree from edges only
__device__ int   g_offs[N_MAX + 1];             // CSR offsets (by dst)
__device__ int   g_cursor[N_MAX];
__device__ int   g_csr[E_MAX];                  // src node per CSR slot

// ---------------- zero degrees ----------------
__global__ void zero_deg_kernel(int n) {
    int i = blockIdx.x * blockDim.x + threadIdx.x;
    if (i < n) g_dege[i] = 0;
}

// ---------------- degree count (edge_index is int32! JAX x64-disabled
// downgrades the reference's int64 request to int32) ----------------
__global__ void count_kernel(const int* __restrict__ dst, int E, int n) {
    int e = blockIdx.x * blockDim.x + threadIdx.x;
    if (e < E) {
        int d = dst[e];
        if ((unsigned)d < (unsigned)n)   // guard: trap-proof
            atomicAdd(&g_dege[d], 1);
    }
}

// ---------------- dinv = rsqrt(deg_edges + 1 self loop) ----------------
__global__ void dinv_kernel(int n) {
    int i = blockIdx.x * blockDim.x + threadIdx.x;
    if (i < n) g_dinv[i] = rsqrtf((float)(g_dege[i] + 1));
}

// ---------------- single-block exclusive scan over degrees ----------------
__global__ void scan_kernel(int n) {
    __shared__ int smem_warp[32];
    __shared__ int s_carry;
    int tid = threadIdx.x;
    if (tid == 0) s_carry = 0;
    __syncthreads();
    for (int base = 0; base < n; base += 1024) {
        int i = base + tid;
        int v = (i < n) ? g_dege[i] : 0;
        int x = v;
        #pragma unroll
        for (int d = 1; d < 32; d <<= 1) {
            int t = __shfl_up_sync(0xffffffffu, x, d);
            if ((tid & 31) >= d) x += t;
        }
        if ((tid & 31) == 31) smem_warp[tid >> 5] = x;
        __syncthreads();
        if (tid < 32) {
            int y = smem_warp[tid];
            #pragma unroll
            for (int d = 1; d < 32; d <<= 1) {
                int t = __shfl_up_sync(0xffffffffu, y, d);
                if (tid >= d) y += t;
            }
            smem_warp[tid] = y;
        }
        __syncthreads();
        int warp_excl = (tid >= 32) ? smem_warp[(tid >> 5) - 1] : 0;
        int incl = x + warp_excl + s_carry;
        if (i < n) {
            g_offs[i]   = incl - v;
            g_cursor[i] = incl - v;
        }
        __syncthreads();
        if (tid == 1023) s_carry = incl;
        __syncthreads();
    }
    if (tid == 0) g_offs[n] = s_carry;
}

// ---------------- counting-sort fill of CSR ----------------
__global__ void fill_kernel(const int* __restrict__ src,
                            const int* __restrict__ dst, int E, int n) {
    int e = blockIdx.x * blockDim.x + threadIdx.x;
    if (e < E) {
        int d = dst[e];
        int s = src[e];
        if ((unsigned)d < (unsigned)n && (unsigned)s < (unsigned)n) {
            int p = atomicAdd(&g_cursor[d], 1);
            g_csr[p] = s;
        }
    }
}

// ---------------- register-tiled SGEMM body, K = 128 fixed ----------------
// C[M,N] = A[M,128] @ B[128,N]
__device__ __forceinline__ void gemm_body(const float* __restrict__ A,
                                          const float* __restrict__ B,
                                          float* __restrict__ C,
                                          int M, int N) {
    constexpr int K = 128, BM = 64, BK = 16;
    __shared__ __align__(16) float As[BK][BM + 4];
    __shared__ __align__(16) float Bs[BK][64 + 8];
    int tid = threadIdx.x;
    int bm = blockIdx.y * BM, bn = blockIdx.x * 64;
    int ty = tid >> 4, tx = tid & 15;
    int arow = tid >> 2, acol = (tid & 3) * 4;
    int brow = tid >> 4, bcol = (tid & 15) * 4;

    float acc[4][4];
    #pragma unroll
    for (int i = 0; i < 4; i++)
        #pragma unroll
        for (int j = 0; j < 4; j++) acc[i][j] = 0.f;

    for (int k0 = 0; k0 < K; k0 += BK) {
        float4 av = make_float4(0.f, 0.f, 0.f, 0.f);
        int gr = bm + arow;
        if (gr < M)
            av = *reinterpret_cast<const float4*>(A + (size_t)gr * K + k0 + acol);
        As[acol + 0][arow] = av.x;
        As[acol + 1][arow] = av.y;
        As[acol + 2][arow] = av.z;
        As[acol + 3][arow] = av.w;
        float4 bv = *reinterpret_cast<const float4*>(B + (size_t)(k0 + brow) * N + bn + bcol);
        Bs[brow][bcol + 0] = bv.x;
        Bs[brow][bcol + 1] = bv.y;
        Bs[brow][bcol + 2] = bv.z;
        Bs[brow][bcol + 3] = bv.w;
        __syncthreads();
        #pragma unroll
        for (int k = 0; k < BK; k++) {
            float rm[4], rn[4];
            #pragma unroll
            for (int i = 0; i < 4; i++) rm[i] = As[k][ty * 4 + i];
            #pragma unroll
            for (int j = 0; j < 4; j++) rn[j] = Bs[k][tx * 4 + j];
            #pragma unroll
            for (int i = 0; i < 4; i++)
                #pragma unroll
                for (int j = 0; j < 4; j++) acc[i][j] += rm[i] * rn[j];
        }
        __syncthreads();
    }
    #pragma unroll
    for (int i = 0; i < 4; i++) {
        int r = bm + ty * 4 + i;
        if (r < M) {
            #pragma unroll
            for (int j = 0; j < 4; j++)
                C[(size_t)r * N + bn + tx * 4 + j] = acc[i][j];
        }
    }
}

// Wrappers binding scratch by symbol.
__global__ __launch_bounds__(256) void sgemm1_kernel(const float* __restrict__ x,
                                                     const float* __restrict__ W1,
                                                     int M) {
    gemm_body(x, W1, g_h1, M, C_HID);
}
__global__ __launch_bounds__(256) void sgemm2_kernel(const float* __restrict__ W2,
                                                     int M) {
    gemm_body(g_a, W2, g_h2, M, C_OUT);
}

// ---------------- aggregation: one warp per dst node, F = 128, +bias+ReLU ----
__global__ void agg128_relu(const float* __restrict__ bias, int n) {
    int w = (blockIdx.x * blockDim.x + threadIdx.x) >> 5;
    if (w >= n) return;
    int lane = threadIdx.x & 31;
    const float* h = g_h1;
    float di = g_dinv[w];
    float sw = di * di;
    float4 hv = reinterpret_cast<const float4*>(h + (size_t)w * 128)[lane];
    float4 acc = make_float4(hv.x * sw, hv.y * sw, hv.z * sw, hv.w * sw);
    int e = g_offs[w], end = g_offs[w + 1];
    for (; e + 1 < end; e += 2) {
        int s0 = g_csr[e], s1 = g_csr[e + 1];
        float w0 = g_dinv[s0] * di, w1 = g_dinv[s1] * di;
        float4 v0 = reinterpret_cast<const float4*>(h + (size_t)s0 * 128)[lane];
        float4 v1 = reinterpret_cast<const float4*>(h + (size_t)s1 * 128)[lane];
        acc.x += v0.x * w0; acc.y += v0.y * w0; acc.z += v0.z * w0; acc.w += v0.w * w0;
        acc.x += v1.x * w1; acc.y += v1.y * w1; acc.z += v1.z * w1; acc.w += v1.w * w1;
    }
    if (e < end) {
        int s = g_csr[e];
        float wg = g_dinv[s] * di;
        float4 v = reinterpret_cast<const float4*>(h + (size_t)s * 128)[lane];
        acc.x += v.x * wg; acc.y += v.y * wg; acc.z += v.z * wg; acc.w += v.w * wg;
    }
    float4 b = reinterpret_cast<const float4*>(bias)[lane];
    acc.x = fmaxf(acc.x + b.x, 0.f);
    acc.y = fmaxf(acc.y + b.y, 0.f);
    acc.z = fmaxf(acc.z + b.z, 0.f);
    acc.w = fmaxf(acc.w + b.w, 0.f);
    reinterpret_cast<float4*>(g_a + (size_t)w * 128)[lane] = acc;
}

// ---------------- aggregation: one warp per dst node, F = 64, +bias ----------
__global__ void agg64_bias(const float* __restrict__ bias,
                           float* __restrict__ out, int n) {
    int w = (blockIdx.x * blockDim.x + threadIdx.x) >> 5;
    if (w >= n) return;
    int lane = threadIdx.x & 31;
    const float* h = g_h2;
    float di = g_dinv[w];
    float sw = di * di;
    float2 hv = reinterpret_cast<const float2*>(h + (size_t)w * 64)[lane];
    float2 acc = make_float2(hv.x * sw, hv.y * sw);
    int e = g_offs[w], end = g_offs[w + 1];
    for (; e + 1 < end; e += 2) {
        int s0 = g_csr[e], s1 = g_csr[e + 1];
        float w0 = g_dinv[s0] * di, w1 = g_dinv[s1] * di;
        float2 v0 = reinterpret_cast<const float2*>(h + (size_t)s0 * 64)[lane];
        float2 v1 = reinterpret_cast<const float2*>(h + (size_t)s1 * 64)[lane];
        acc.x += v0.x * w0; acc.y += v0.y * w0;
        acc.x += v1.x * w1; acc.y += v1.y * w1;
    }
    if (e < end) {
        int s = g_csr[e];
        float wg = g_dinv[s] * di;
        float2 v = reinterpret_cast<const float2*>(h + (size_t)s * 64)[lane];
        acc.x += v.x * wg; acc.y += v.y * wg;
    }
    float2 b = reinterpret_cast<const float2*>(bias)[lane];
    acc.x += b.x; acc.y += b.y;
    reinterpret_cast<float2*>(out + (size_t)w * 64)[lane] = acc;
}

// ---------------- host launch: kernel launches ONLY ----------------
extern "C" void kernel_launch(void* const* d_in, const int* in_sizes, int n_in,
                              void* d_out, int out_size) {
    const float* x  = (const float*)d_in[0];
    const int*   ei = (const int*)d_in[1];     // int32 edge_index (JAX x64 off)
    const float* W1 = (const float*)d_in[2];
    const float* b1 = (const float*)d_in[3];
    const float* W2 = (const float*)d_in[4];
    const float* b2 = (const float*)d_in[5];
    float*       out = (float*)d_out;

    const int n = in_sizes[0] / C_IN;   // 50000
    const int E = in_sizes[1] / 2;      // 800000
    const int* srcp = ei;
    const int* dstp = ei + E;

    // 1) degrees
    zero_deg_kernel<<<(n + 255) / 256, 256>>>(n);
    count_kernel<<<(E + 255) / 256, 256>>>(dstp, E, n);
    // 2) dinv + CSR offsets + fill
    dinv_kernel<<<(n + 255) / 256, 256>>>(n);
    scan_kernel<<<1, 1024>>>(n);
    fill_kernel<<<(E + 255) / 256, 256>>>(srcp, dstp, E, n);
    // 3) layer 1: GEMM + aggregate(+bias+relu)
    {
        dim3 grid(C_HID / 64, (n + 63) / 64);
        sgemm1_kernel<<<grid, 256>>>(x, W1, n);
    }
    agg128_relu<<<(n * 32 + 255) / 256, 256>>>(b1, n);
    // 4) layer 2: GEMM + aggregate(+bias)
    {
        dim3 grid(C_OUT / 64, (n + 63) / 64);
        sgemm2_kernel<<<grid, 256>>>(W2, n);
    }
    agg64_bias<<<(n * 32 + 255) / 256, 256>>>(b2, out, n);
}

// round 5
// speedup vs baseline: 1.1395x; 1.1395x over previous
#include <cuda_runtime.h>
#include <cstdint>

// Problem constants (fixed by the dataset)
#define N_MAX 50000
#define E_MAX 800000
#define C_IN  128
#define C_HID 128
#define C_OUT 64

#define SCAN_BLK 512
#define SCAN_NB  ((N_MAX + SCAN_BLK - 1) / SCAN_BLK)   // 98

// ---------------- scratch (static __device__) ----------------
__device__ float g_h1[(size_t)N_MAX * C_HID];   // x @ W1
__device__ float g_a [(size_t)N_MAX * C_HID];   // relu(agg1 + b1)
__device__ float g_h2[(size_t)N_MAX * C_OUT];   // a @ W2
__device__ float g_dinv[N_MAX];
__device__ int   g_dege[N_MAX];                 // in-degree from edges only
__device__ int   g_offs[N_MAX + 1];             // CSR offsets (by dst)
__device__ int   g_cursor[N_MAX];
__device__ int   g_csr[E_MAX];                  // src node per CSR slot
__device__ int   g_bsum[128];                   // per-block degree sums

// ---------------- zero degrees ----------------
__global__ void zero_deg_kernel(int n) {
    int i = blockIdx.x * blockDim.x + threadIdx.x;
    if (i < n) g_dege[i] = 0;
}

// ---------------- degree count (edge_index is int32) ----------------
__global__ void count_kernel(const int* __restrict__ dst, int E, int n) {
    int e = blockIdx.x * blockDim.x + threadIdx.x;
    if (e < E) {
        int d = dst[e];
        if ((unsigned)d < (unsigned)n)
            atomicAdd(&g_dege[d], 1);
    }
}

// ---------------- scan pass 1: per-block degree sums (+ fused dinv) --------
__global__ void scan_pass1(int n) {
    __shared__ int s_warp[SCAN_BLK / 32];
    int tid = threadIdx.x;
    int i = blockIdx.x * SCAN_BLK + tid;
    int v = 0;
    if (i < n) {
        v = g_dege[i];
        g_dinv[i] = rsqrtf((float)(v + 1));   // fused dinv
    }
    int x = v;
    #pragma unroll
    for (int d = 16; d > 0; d >>= 1) x += __shfl_down_sync(0xffffffffu, x, d);
    if ((tid & 31) == 0) s_warp[tid >> 5] = x;
    __syncthreads();
    if (tid < SCAN_BLK / 32) {
        int y = s_warp[tid];
        #pragma unroll
        for (int d = 8; d > 0; d >>= 1) y += __shfl_down_sync(0xffffu, y, d);
        if (tid == 0) g_bsum[blockIdx.x] = y;
    }
}

// ---------------- scan pass 2: exclusive scan of block sums (1 block) ------
__global__ void scan_pass2(int nb, int n) {
    __shared__ int s_warp[4];
    int tid = threadIdx.x;            // 128 threads
    int v = (tid < nb) ? g_bsum[tid] : 0;
    int x = v;
    #pragma unroll
    for (int d = 1; d < 32; d <<= 1) {
        int t = __shfl_up_sync(0xffffffffu, x, d);
        if ((tid & 31) >= d) x += t;
    }
    if ((tid & 31) == 31) s_warp[tid >> 5] = x;
    __syncthreads();
    if (tid < 4) {
        int y = s_warp[tid];
        #pragma unroll
        for (int d = 1; d < 4; d <<= 1) {
            int t = __shfl_up_sync(0xfu, y, d);
            if (tid >= d) y += t;
        }
        s_warp[tid] = y;
    }
    __syncthreads();
    int excl = x - v + ((tid >= 32) ? s_warp[(tid >> 5) - 1] : 0);
    if (tid < nb) g_bsum[tid] = excl;
    if (tid == 127) g_offs[n] = excl + v;   // total edge count kept
}

// ---------------- scan pass 3: per-block local scan + block offset ---------
__global__ void scan_pass3(int n) {
    __shared__ int s_warp[SCAN_BLK / 32];
    int tid = threadIdx.x;
    int i = blockIdx.x * SCAN_BLK + tid;
    int v = (i < n) ? g_dege[i] : 0;
    int x = v;
    #pragma unroll
    for (int d = 1; d < 32; d <<= 1) {
        int t = __shfl_up_sync(0xffffffffu, x, d);
        if ((tid & 31) >= d) x += t;
    }
    if ((tid & 31) == 31) s_warp[tid >> 5] = x;
    __syncthreads();
    if (tid < SCAN_BLK / 32) {
        int y = s_warp[tid];
        #pragma unroll
        for (int d = 1; d < SCAN_BLK / 32; d <<= 1) {
            int t = __shfl_up_sync(0xffffu, y, d);
            if (tid >= d) y += t;
        }
        s_warp[tid] = y;
    }
    __syncthreads();
    int excl = x - v + ((tid >= 32) ? s_warp[(tid >> 5) - 1] : 0) + g_bsum[blockIdx.x];
    if (i < n) {
        g_offs[i]   = excl;
        g_cursor[i] = excl;
    }
}

// ---------------- counting-sort fill of CSR ----------------
__global__ void fill_kernel(const int* __restrict__ src,
                            const int* __restrict__ dst, int E, int n) {
    int e = blockIdx.x * blockDim.x + threadIdx.x;
    if (e < E) {
        int d = dst[e];
        int s = src[e];
        if ((unsigned)d < (unsigned)n && (unsigned)s < (unsigned)n) {
            int p = atomicAdd(&g_cursor[d], 1);
            g_csr[p] = s;
        }
    }
}

// ---------------- SGEMM: BM=128, BK=8, 256 threads, 8x(BN/16) per thread ---
// C[M,N] = A[M,128] @ B[128,N]; N multiple of BN
template <int BN>
__device__ __forceinline__ void gemm_body(const float* __restrict__ A,
                                          const float* __restrict__ B,
                                          float* __restrict__ C,
                                          int M, int N) {
    constexpr int K = 128, BM = 128, BK = 8;
    constexpr int CN = BN / 16;                 // cols per thread (8 or 4)
    __shared__ __align__(16) float As[BK][BM + 4];
    __shared__ __align__(16) float Bs[BK][BN + 4];
    int tid = threadIdx.x;
    int bm = blockIdx.y * BM, bn = blockIdx.x * BN;
    int ty = tid >> 4, tx = tid & 15;           // 16x16 thread grid
    int arow = tid >> 1, acol = (tid & 1) * 4;  // A: 128 rows x 8 cols

    float acc[8][CN];
    #pragma unroll
    for (int i = 0; i < 8; i++)
        #pragma unroll
        for (int j = 0; j < CN; j++) acc[i][j] = 0.f;

    for (int k0 = 0; k0 < K; k0 += BK) {
        // load A tile (transposed into As[k][m])
        float4 av = make_float4(0.f, 0.f, 0.f, 0.f);
        int gr = bm + arow;
        if (gr < M)
            av = *reinterpret_cast<const float4*>(A + (size_t)gr * K + k0 + acol);
        As[acol + 0][arow] = av.x;
        As[acol + 1][arow] = av.y;
        As[acol + 2][arow] = av.z;
        As[acol + 3][arow] = av.w;
        // load B tile: BK x BN
        if (BN == 128 || tid < 128) {
            int brow, bcol;
            if (BN == 128) { brow = tid >> 5; bcol = (tid & 31) * 4; }
            else           { brow = tid >> 4; bcol = (tid & 15) * 4; }
            float4 bv = *reinterpret_cast<const float4*>(B + (size_t)(k0 + brow) * N + bn + bcol);
            Bs[brow][bcol + 0] = bv.x;
            Bs[brow][bcol + 1] = bv.y;
            Bs[brow][bcol + 2] = bv.z;
            Bs[brow][bcol + 3] = bv.w;
        }
        __syncthreads();
        #pragma unroll
        for (int k = 0; k < BK; k++) {
            float rm[8], rn[CN];
            #pragma unroll
            for (int i = 0; i < 8; i++) rm[i] = As[k][ty * 8 + i];
            #pragma unroll
            for (int j = 0; j < CN; j++) rn[j] = Bs[k][tx * CN + j];
            #pragma unroll
            for (int i = 0; i < 8; i++)
                #pragma unroll
                for (int j = 0; j < CN; j++) acc[i][j] += rm[i] * rn[j];
        }
        __syncthreads();
    }
    #pragma unroll
    for (int i = 0; i < 8; i++) {
        int r = bm + ty * 8 + i;
        if (r < M) {
            #pragma unroll
            for (int j = 0; j < CN; j += 4)
                *reinterpret_cast<float4*>(C + (size_t)r * N + bn + tx * CN + j) =
                    make_float4(acc[i][j], acc[i][j + 1], acc[i][j + 2], acc[i][j + 3]);
        }
    }
}

__global__ __launch_bounds__(256) void sgemm1_kernel(const float* __restrict__ x,
                                                     const float* __restrict__ W1,
                                                     int M) {
    gemm_body<128>(x, W1, g_h1, M, C_HID);
}
__global__ __launch_bounds__(256) void sgemm2_kernel(const float* __restrict__ W2,
                                                     int M) {
    gemm_body<64>(g_a, W2, g_h2, M, C_OUT);
}

// ---------------- aggregation: one warp per dst node, F = 128, +bias+ReLU ----
__global__ void agg128_relu(const float* __restrict__ bias, int n) {
    int w = (blockIdx.x * blockDim.x + threadIdx.x) >> 5;
    if (w >= n) return;
    int lane = threadIdx.x & 31;
    const float* h = g_h1;
    float di = g_dinv[w];
    float sw = di * di;
    float4 hv = reinterpret_cast<const float4*>(h + (size_t)w * 128)[lane];
    float4 acc = make_float4(hv.x * sw, hv.y * sw, hv.z * sw, hv.w * sw);
    int e = g_offs[w], end = g_offs[w + 1];
    for (; e + 1 < end; e += 2) {
        int s0 = g_csr[e], s1 = g_csr[e + 1];
        float w0 = g_dinv[s0] * di, w1 = g_dinv[s1] * di;
        float4 v0 = reinterpret_cast<const float4*>(h + (size_t)s0 * 128)[lane];
        float4 v1 = reinterpret_cast<const float4*>(h + (size_t)s1 * 128)[lane];
        acc.x += v0.x * w0; acc.y += v0.y * w0; acc.z += v0.z * w0; acc.w += v0.w * w0;
        acc.x += v1.x * w1; acc.y += v1.y * w1; acc.z += v1.z * w1; acc.w += v1.w * w1;
    }
    if (e < end) {
        int s = g_csr[e];
        float wg = g_dinv[s] * di;
        float4 v = reinterpret_cast<const float4*>(h + (size_t)s * 128)[lane];
        acc.x += v.x * wg; acc.y += v.y * wg; acc.z += v.z * wg; acc.w += v.w * wg;
    }
    float4 b = reinterpret_cast<const float4*>(bias)[lane];
    acc.x = fmaxf(acc.x + b.x, 0.f);
    acc.y = fmaxf(acc.y + b.y, 0.f);
    acc.z = fmaxf(acc.z + b.z, 0.f);
    acc.w = fmaxf(acc.w + b.w, 0.f);
    reinterpret_cast<float4*>(g_a + (size_t)w * 128)[lane] = acc;
}

// ---------------- aggregation: one warp per dst node, F = 64, +bias ----------
__global__ void agg64_bias(const float* __restrict__ bias,
                           float* __restrict__ out, int n) {
    int w = (blockIdx.x * blockDim.x + threadIdx.x) >> 5;
    if (w >= n) return;
    int lane = threadIdx.x & 31;
    const float* h = g_h2;
    float di = g_dinv[w];
    float sw = di * di;
    float2 hv = reinterpret_cast<const float2*>(h + (size_t)w * 64)[lane];
    float2 acc = make_float2(hv.x * sw, hv.y * sw);
    int e = g_offs[w], end = g_offs[w + 1];
    for (; e + 1 < end; e += 2) {
        int s0 = g_csr[e], s1 = g_csr[e + 1];
        float w0 = g_dinv[s0] * di, w1 = g_dinv[s1] * di;
        float2 v0 = reinterpret_cast<const float2*>(h + (size_t)s0 * 64)[lane];
        float2 v1 = reinterpret_cast<const float2*>(h + (size_t)s1 * 64)[lane];
        acc.x += v0.x * w0; acc.y += v0.y * w0;
        acc.x += v1.x * w1; acc.y += v1.y * w1;
    }
    if (e < end) {
        int s = g_csr[e];
        float wg = g_dinv[s] * di;
        float2 v = reinterpret_cast<const float2*>(h + (size_t)s * 64)[lane];
        acc.x += v.x * wg; acc.y += v.y * wg;
    }
    float2 b = reinterpret_cast<const float2*>(bias)[lane];
    acc.x += b.x; acc.y += b.y;
    reinterpret_cast<float2*>(out + (size_t)w * 64)[lane] = acc;
}

// ---------------- host launch: kernel launches ONLY ----------------
extern "C" void kernel_launch(void* const* d_in, const int* in_sizes, int n_in,
                              void* d_out, int out_size) {
    const float* x  = (const float*)d_in[0];
    const int*   ei = (const int*)d_in[1];     // int32 edge_index
    const float* W1 = (const float*)d_in[2];
    const float* b1 = (const float*)d_in[3];
    const float* W2 = (const float*)d_in[4];
    const float* b2 = (const float*)d_in[5];
    float*       out = (float*)d_out;

    const int n = in_sizes[0] / C_IN;   // 50000
    const int E = in_sizes[1] / 2;      // 800000
    const int* srcp = ei;
    const int* dstp = ei + E;
    const int nb = (n + SCAN_BLK - 1) / SCAN_BLK;

    // 1) degrees
    zero_deg_kernel<<<(n + 255) / 256, 256>>>(n);
    count_kernel<<<(E + 255) / 256, 256>>>(dstp, E, n);
    // 2) dinv (fused) + CSR offsets (3-pass scan) + fill
    scan_pass1<<<nb, SCAN_BLK>>>(n);
    scan_pass2<<<1, 128>>>(nb, n);
    scan_pass3<<<nb, SCAN_BLK>>>(n);
    fill_kernel<<<(E + 255) / 256, 256>>>(srcp, dstp, E, n);
    // 3) layer 1: GEMM + aggregate(+bias+relu)
    {
        dim3 grid(C_HID / 128, (n + 127) / 128);
        sgemm1_kernel<<<grid, 256>>>(x, W1, n);
    }
    agg128_relu<<<(n * 32 + 255) / 256, 256>>>(b1, n);
    // 4) layer 2: GEMM + aggregate(+bias)
    {
        dim3 grid(C_OUT / 64, (n + 127) / 128);
        sgemm2_kernel<<<grid, 256>>>(W2, n);
    }
    agg64_bias<<<(n * 32 + 255) / 256, 256>>>(b2, out, n);
}

// round 6
// speedup vs baseline: 1.2876x; 1.1300x over previous
#include <cuda_runtime.h>
#include <cstdint>

// Problem constants (fixed by the dataset)
#define N_MAX 50000
#define E_MAX 800000
#define C_IN  128
#define C_HID 128
#define C_OUT 64

#define SCAN_BLK 512

// ---------------- scratch (static __device__) ----------------
__device__ float g_h1[(size_t)N_MAX * C_HID];   // x @ W1
__device__ float g_a [(size_t)N_MAX * C_HID];   // relu(agg1 + b1)
__device__ float g_h2[(size_t)N_MAX * C_OUT];   // a @ W2
__device__ float g_dinv[N_MAX];
__device__ int   g_dege[N_MAX];                 // in-degree from edges only
__device__ int   g_offs[N_MAX + 1];             // CSR offsets (by dst)
__device__ int   g_cursor[N_MAX];
__device__ int   g_csr[E_MAX];                  // src node per CSR slot
__device__ int   g_bsum[128];                   // per-block degree sums

// ---------------- zero degrees ----------------
__global__ void zero_deg_kernel(int n) {
    int i = blockIdx.x * blockDim.x + threadIdx.x;
    if (i < n) g_dege[i] = 0;
}

// ---------------- degree count (edge_index is int32) ----------------
__global__ void count_kernel(const int* __restrict__ dst, int E, int n) {
    int e = blockIdx.x * blockDim.x + threadIdx.x;
    if (e < E) {
        int d = dst[e];
        if ((unsigned)d < (unsigned)n)
            atomicAdd(&g_dege[d], 1);
    }
}

// ---------------- scan pass 1: per-block degree sums (+ fused dinv) --------
__global__ void scan_pass1(int n) {
    __shared__ int s_warp[SCAN_BLK / 32];
    int tid = threadIdx.x;
    int i = blockIdx.x * SCAN_BLK + tid;
    int v = 0;
    if (i < n) {
        v = g_dege[i];
        g_dinv[i] = rsqrtf((float)(v + 1));   // fused dinv
    }
    int x = v;
    #pragma unroll
    for (int d = 16; d > 0; d >>= 1) x += __shfl_down_sync(0xffffffffu, x, d);
    if ((tid & 31) == 0) s_warp[tid >> 5] = x;
    __syncthreads();
    if (tid < SCAN_BLK / 32) {
        int y = s_warp[tid];
        #pragma unroll
        for (int d = 8; d > 0; d >>= 1) y += __shfl_down_sync(0xffffu, y, d);
        if (tid == 0) g_bsum[blockIdx.x] = y;
    }
}

// ---------------- scan pass 2: exclusive scan of block sums (1 block) ------
__global__ void scan_pass2(int nb, int n) {
    __shared__ int s_warp[4];
    int tid = threadIdx.x;            // 128 threads
    int v = (tid < nb) ? g_bsum[tid] : 0;
    int x = v;
    #pragma unroll
    for (int d = 1; d < 32; d <<= 1) {
        int t = __shfl_up_sync(0xffffffffu, x, d);
        if ((tid & 31) >= d) x += t;
    }
    if ((tid & 31) == 31) s_warp[tid >> 5] = x;
    __syncthreads();
    if (tid < 4) {
        int y = s_warp[tid];
        #pragma unroll
        for (int d = 1; d < 4; d <<= 1) {
            int t = __shfl_up_sync(0xfu, y, d);
            if (tid >= d) y += t;
        }
        s_warp[tid] = y;
    }
    __syncthreads();
    int excl = x - v + ((tid >= 32) ? s_warp[(tid >> 5) - 1] : 0);
    if (tid < nb) g_bsum[tid] = excl;
    if (tid == 127) g_offs[n] = excl + v;
}

// ---------------- scan pass 3: per-block local scan + block offset ---------
__global__ void scan_pass3(int n) {
    __shared__ int s_warp[SCAN_BLK / 32];
    int tid = threadIdx.x;
    int i = blockIdx.x * SCAN_BLK + tid;
    int v = (i < n) ? g_dege[i] : 0;
    int x = v;
    #pragma unroll
    for (int d = 1; d < 32; d <<= 1) {
        int t = __shfl_up_sync(0xffffffffu, x, d);
        if ((tid & 31) >= d) x += t;
    }
    if ((tid & 31) == 31) s_warp[tid >> 5] = x;
    __syncthreads();
    if (tid < SCAN_BLK / 32) {
        int y = s_warp[tid];
        #pragma unroll
        for (int d = 1; d < SCAN_BLK / 32; d <<= 1) {
            int t = __shfl_up_sync(0xffffu, y, d);
            if (tid >= d) y += t;
        }
        s_warp[tid] = y;
    }
    __syncthreads();
    int excl = x - v + ((tid >= 32) ? s_warp[(tid >> 5) - 1] : 0) + g_bsum[blockIdx.x];
    if (i < n) {
        g_offs[i]   = excl;
        g_cursor[i] = excl;
    }
}

// ---------------- counting-sort fill of CSR ----------------
__global__ void fill_kernel(const int* __restrict__ src,
                            const int* __restrict__ dst, int E, int n) {
    int e = blockIdx.x * blockDim.x + threadIdx.x;
    if (e < E) {
        int d = dst[e];
        int s = src[e];
        if ((unsigned)d < (unsigned)n && (unsigned)s < (unsigned)n) {
            int p = atomicAdd(&g_cursor[d], 1);
            g_csr[p] = s;
        }
    }
}

// ---------------- SGEMM: BM=128, BK=8, 256 threads ----------------
template <int BN>
__device__ __forceinline__ void gemm_body(const float* __restrict__ A,
                                          const float* __restrict__ B,
                                          float* __restrict__ C,
                                          int M, int N) {
    constexpr int K = 128, BM = 128, BK = 8;
    constexpr int CN = BN / 16;                 // cols per thread (8 or 4)
    __shared__ __align__(16) float As[BK][BM + 4];
    __shared__ __align__(16) float Bs[BK][BN + 4];
    int tid = threadIdx.x;
    int bm = blockIdx.y * BM, bn = blockIdx.x * BN;
    int ty = tid >> 4, tx = tid & 15;           // 16x16 thread grid
    int arow = tid >> 1, acol = (tid & 1) * 4;  // A: 128 rows x 8 cols

    float acc[8][CN];
    #pragma unroll
    for (int i = 0; i < 8; i++)
        #pragma unroll
        for (int j = 0; j < CN; j++) acc[i][j] = 0.f;

    for (int k0 = 0; k0 < K; k0 += BK) {
        float4 av = make_float4(0.f, 0.f, 0.f, 0.f);
        int gr = bm + arow;
        if (gr < M)
            av = *reinterpret_cast<const float4*>(A + (size_t)gr * K + k0 + acol);
        As[acol + 0][arow] = av.x;
        As[acol + 1][arow] = av.y;
        As[acol + 2][arow] = av.z;
        As[acol + 3][arow] = av.w;
        if (BN == 128 || tid < 128) {
            int brow, bcol;
            if (BN == 128) { brow = tid >> 5; bcol = (tid & 31) * 4; }
            else           { brow = tid >> 4; bcol = (tid & 15) * 4; }
            float4 bv = *reinterpret_cast<const float4*>(B + (size_t)(k0 + brow) * N + bn + bcol);
            Bs[brow][bcol + 0] = bv.x;
            Bs[brow][bcol + 1] = bv.y;
            Bs[brow][bcol + 2] = bv.z;
            Bs[brow][bcol + 3] = bv.w;
        }
        __syncthreads();
        #pragma unroll
        for (int k = 0; k < BK; k++) {
            float rm[8], rn[CN];
            #pragma unroll
            for (int i = 0; i < 8; i++) rm[i] = As[k][ty * 8 + i];
            #pragma unroll
            for (int j = 0; j < CN; j++) rn[j] = Bs[k][tx * CN + j];
            #pragma unroll
            for (int i = 0; i < 8; i++)
                #pragma unroll
                for (int j = 0; j < CN; j++) acc[i][j] += rm[i] * rn[j];
        }
        __syncthreads();
    }
    #pragma unroll
    for (int i = 0; i < 8; i++) {
        int r = bm + ty * 8 + i;
        if (r < M) {
            #pragma unroll
            for (int j = 0; j < CN; j += 4)
                *reinterpret_cast<float4*>(C + (size_t)r * N + bn + tx * CN + j) =
                    make_float4(acc[i][j], acc[i][j + 1], acc[i][j + 2], acc[i][j + 3]);
        }
    }
}

__global__ __launch_bounds__(256) void sgemm1_kernel(const float* __restrict__ x,
                                                     const float* __restrict__ W1,
                                                     int M) {
    gemm_body<128>(x, W1, g_h1, M, C_HID);
}
__global__ __launch_bounds__(256) void sgemm2_kernel(const float* __restrict__ W2,
                                                     int M) {
    gemm_body<64>(g_a, W2, g_h2, M, C_OUT);
}

// ---------------- aggregation: one warp per dst node, F = 128, +bias+ReLU ----
// 4-edge unroll for deeper MLP (L2 latency hiding)
__global__ __launch_bounds__(256) void agg128_relu(const float* __restrict__ bias, int n) {
    int w = (blockIdx.x * blockDim.x + threadIdx.x) >> 5;
    if (w >= n) return;
    int lane = threadIdx.x & 31;
    const float* h = g_h1;
    float di = g_dinv[w];
    float sw = di * di;
    float4 hv = reinterpret_cast<const float4*>(h + (size_t)w * 128)[lane];
    float4 acc = make_float4(hv.x * sw, hv.y * sw, hv.z * sw, hv.w * sw);
    int e = g_offs[w], end = g_offs[w + 1];
    for (; e + 3 < end; e += 4) {
        int s0 = g_csr[e], s1 = g_csr[e + 1], s2 = g_csr[e + 2], s3 = g_csr[e + 3];
        float w0 = g_dinv[s0] * di, w1 = g_dinv[s1] * di;
        float w2 = g_dinv[s2] * di, w3 = g_dinv[s3] * di;
        float4 v0 = reinterpret_cast<const float4*>(h + (size_t)s0 * 128)[lane];
        float4 v1 = reinterpret_cast<const float4*>(h + (size_t)s1 * 128)[lane];
        float4 v2 = reinterpret_cast<const float4*>(h + (size_t)s2 * 128)[lane];
        float4 v3 = reinterpret_cast<const float4*>(h + (size_t)s3 * 128)[lane];
        acc.x += v0.x * w0; acc.y += v0.y * w0; acc.z += v0.z * w0; acc.w += v0.w * w0;
        acc.x += v1.x * w1; acc.y += v1.y * w1; acc.z += v1.z * w1; acc.w += v1.w * w1;
        acc.x += v2.x * w2; acc.y += v2.y * w2; acc.z += v2.z * w2; acc.w += v2.w * w2;
        acc.x += v3.x * w3; acc.y += v3.y * w3; acc.z += v3.z * w3; acc.w += v3.w * w3;
    }
    for (; e < end; e++) {
        int s = g_csr[e];
        float wg = g_dinv[s] * di;
        float4 v = reinterpret_cast<const float4*>(h + (size_t)s * 128)[lane];
        acc.x += v.x * wg; acc.y += v.y * wg; acc.z += v.z * wg; acc.w += v.w * wg;
    }
    float4 b = reinterpret_cast<const float4*>(bias)[lane];
    acc.x = fmaxf(acc.x + b.x, 0.f);
    acc.y = fmaxf(acc.y + b.y, 0.f);
    acc.z = fmaxf(acc.z + b.z, 0.f);
    acc.w = fmaxf(acc.w + b.w, 0.f);
    reinterpret_cast<float4*>(g_a + (size_t)w * 128)[lane] = acc;
}

// ---------------- aggregation: one warp per dst node, F = 64, +bias ----------
__global__ __launch_bounds__(256) void agg64_bias(const float* __restrict__ bias,
                                                  float* __restrict__ out, int n) {
    int w = (blockIdx.x * blockDim.x + threadIdx.x) >> 5;
    if (w >= n) return;
    int lane = threadIdx.x & 31;
    const float* h = g_h2;
    float di = g_dinv[w];
    float sw = di * di;
    float2 hv = reinterpret_cast<const float2*>(h + (size_t)w * 64)[lane];
    float2 acc = make_float2(hv.x * sw, hv.y * sw);
    int e = g_offs[w], end = g_offs[w + 1];
    for (; e + 3 < end; e += 4) {
        int s0 = g_csr[e], s1 = g_csr[e + 1], s2 = g_csr[e + 2], s3 = g_csr[e + 3];
        float w0 = g_dinv[s0] * di, w1 = g_dinv[s1] * di;
        float w2 = g_dinv[s2] * di, w3 = g_dinv[s3] * di;
        float2 v0 = reinterpret_cast<const float2*>(h + (size_t)s0 * 64)[lane];
        float2 v1 = reinterpret_cast<const float2*>(h + (size_t)s1 * 64)[lane];
        float2 v2 = reinterpret_cast<const float2*>(h + (size_t)s2 * 64)[lane];
        float2 v3 = reinterpret_cast<const float2*>(h + (size_t)s3 * 64)[lane];
        acc.x += v0.x * w0; acc.y += v0.y * w0;
        acc.x += v1.x * w1; acc.y += v1.y * w1;
        acc.x += v2.x * w2; acc.y += v2.y * w2;
        acc.x += v3.x * w3; acc.y += v3.y * w3;
    }
    for (; e < end; e++) {
        int s = g_csr[e];
        float wg = g_dinv[s] * di;
        float2 v = reinterpret_cast<const float2*>(h + (size_t)s * 64)[lane];
        acc.x += v.x * wg; acc.y += v.y * wg;
    }
    float2 b = reinterpret_cast<const float2*>(bias)[lane];
    acc.x += b.x; acc.y += b.y;
    reinterpret_cast<float2*>(out + (size_t)w * 64)[lane] = acc;
}

// ---------------- host launch ----------------
extern "C" void kernel_launch(void* const* d_in, const int* in_sizes, int n_in,
                              void* d_out, int out_size) {
    const float* x  = (const float*)d_in[0];
    const int*   ei = (const int*)d_in[1];     // int32 edge_index
    const float* W1 = (const float*)d_in[2];
    const float* b1 = (const float*)d_in[3];
    const float* W2 = (const float*)d_in[4];
    const float* b2 = (const float*)d_in[5];
    float*       out = (float*)d_out;

    const int n = in_sizes[0] / C_IN;   // 50000
    const int E = in_sizes[1] / 2;      // 800000
    const int* srcp = ei;
    const int* dstp = ei + E;
    const int nb = (n + SCAN_BLK - 1) / SCAN_BLK;

    // lazily-created second stream + fork/join events (host objects, no device mem)
    static cudaStream_t s2 = nullptr;
    static cudaEvent_t ev_fork = nullptr, ev_join = nullptr;
    if (!s2) {
        cudaStreamCreateWithFlags(&s2, cudaStreamNonBlocking);
        cudaEventCreateWithFlags(&ev_fork, cudaEventDisableTiming);
        cudaEventCreateWithFlags(&ev_join, cudaEventDisableTiming);
    }

    // fork: sgemm1 (depends only on x, W1) runs concurrently with CSR build
    cudaEventRecord(ev_fork, 0);
    cudaStreamWaitEvent(s2, ev_fork, 0);
    {
        dim3 grid(C_HID / 128, (n + 127) / 128);
        sgemm1_kernel<<<grid, 256, 0, s2>>>(x, W1, n);
    }
    cudaEventRecord(ev_join, s2);

    // CSR build chain on main stream
    zero_deg_kernel<<<(n + 255) / 256, 256>>>(n);
    count_kernel<<<(E + 255) / 256, 256>>>(dstp, E, n);
    scan_pass1<<<nb, SCAN_BLK>>>(n);
    scan_pass2<<<1, 128>>>(nb, n);
    scan_pass3<<<nb, SCAN_BLK>>>(n);
    fill_kernel<<<(E + 255) / 256, 256>>>(srcp, dstp, E, n);

    // join: aggregation needs both CSR and g_h1
    cudaStreamWaitEvent(0, ev_join, 0);
    agg128_relu<<<(n * 32 + 255) / 256, 256>>>(b1, n);
    // layer 2
    {
        dim3 grid(C_OUT / 64, (n + 127) / 128);
        sgemm2_kernel<<<grid, 256>>>(W2, n);
    }
    agg64_bias<<<(n * 32 + 255) / 256, 256>>>(b2, out, n);
}